// round 3
// baseline (speedup 1.0000x reference)
#include <cuda_runtime.h>

// BWSGODE: 8192-step serial scalar ODE, single-thread latency/issue bound.
//
// v3: partial f32x2 packing. v2 was issue-bound at 14 fma-pipe ops x 2cyc.
// Pack 4 op-pairs into fma.rn.f32x2 (one fma-pipe slot each), chosen so pair
// builds are off the critical chain and state stays packed across iterations:
//   {a1,c} = {-p0,p2}*{G,G} + {p0,-p4}
//   {t,f}  = {1,1}*{W,S} + {B,W}          (exact: 1*x+y == x+y)
//   {nB,nW}= {g,e}*{B,W} + {B,W}
//   {nS,nG}= {b,a}*{S,G} + {S,G}
// Remaining 6 ops scalar. Per-lane math is bit-identical to v2.

__device__ __forceinline__ unsigned long long pk2(float lo, float hi) {
    unsigned long long r;
    asm("mov.b64 %0, {%1, %2};" : "=l"(r) : "f"(lo), "f"(hi));
    return r;
}
__device__ __forceinline__ void upk2(unsigned long long v, float& lo, float& hi) {
    asm("mov.b64 {%0, %1}, %2;" : "=f"(lo), "=f"(hi) : "l"(v));
}
__device__ __forceinline__ unsigned long long fma2(unsigned long long a,
                                                   unsigned long long b,
                                                   unsigned long long c) {
    unsigned long long d;
    asm("fma.rn.f32x2 %0, %1, %2, %3;" : "=l"(d) : "l"(a), "l"(b), "l"(c));
    return d;
}

__global__ void __launch_bounds__(256, 1)
bwsg_ode_kernel(const float* __restrict__ y0,
                const float* __restrict__ p,
                float* __restrict__ out,
                int num_steps) {
    extern __shared__ unsigned long long traj[];  // 2 x u64 per step (float4)

    if (threadIdx.x == 0) {
        float B = y0[0];
        float W = y0[1];
        float S = y0[2];
        float G = y0[3];
        const float iv = y0[4];

        const float p0 = p[0], p2 = p[2], p5 = p[5], p8 = p[8];
        const float np1 = -p[1], np3 = -p[3], np4 = -p[4];
        const float np6 = -p[6], np7 = -p[7], np9 = -p[9];
        const float np0 = -p0;

        const float fi  = (iv != 0.0f) ? 1.0f : 0.0f;
        const float thr = __fsub_rn(__fadd_rn(5.0f, iv), 1.0f);

        // First integer step with mask==1 (see v2 derivation).
        int j0 = 1;
        if (fi != 0.0f) {
            float ct = ceilf(thr);
            if (ct > 1.0f) {
                j0 = (ct >= (float)num_steps) ? num_steps : (int)ct;
            }
        }

        traj[0] = pk2(B, W);
        traj[1] = pk2(S, G);

        // ---- Phase 1: mask == 0 (interventional only), B frozen ----
        for (int j = 1; j < j0; ++j) {
            float a = __fmaf_rn(np0, G, p0);
            a       = __fmaf_rn(np1, S, a);
            float c = __fmaf_rn(p2, G, np4);
            float b = __fmaf_rn(np3, W, c);
            float d = __fmaf_rn(p5, S, np7);
            float e = __fmul_rn(W, d);
            float nS = __fmaf_rn(b, S, S);
            float nW = __fmaf_rn(e, W, W);
            float nG = __fmaf_rn(a, G, G);
            W = nW; S = nS; G = nG;
            traj[2 * j]     = pk2(B, W);
            traj[2 * j + 1] = pk2(S, G);
        }

        // ---- Phase 2: mask == 1, hot loop (10 fma-pipe ops) ----
        const unsigned long long Cm_gg = pk2(np0, p2);   // {-p0, p2}
        const unsigned long long Ca_gg = pk2(p0, np4);   // {p0, -p4}
        const unsigned long long Cone  = pk2(1.0f, 1.0f);

        unsigned long long BW = pk2(B, W);
        unsigned long long SG = pk2(S, G);

        #pragma unroll 8
        for (int j = j0; j < num_steps; ++j) {
            float lB, lW, lS, lG;
            upk2(BW, lB, lW);
            upk2(SG, lS, lG);

            unsigned long long GG = pk2(lG, lG);
            unsigned long long WS = pk2(lW, lS);

            unsigned long long A1C = fma2(Cm_gg, GG, Ca_gg); // {a1, c}
            unsigned long long TF  = fma2(Cone,  WS, BW);    // {t=W+B, f=S+W}

            float a1, c, t, f;
            upk2(A1C, a1, c);
            upk2(TF,  t,  f);

            float a  = __fmaf_rn(np1, lS, a1);   // a1 - p1*S
            float d1 = __fmaf_rn(p5,  lS, np7);  // p5*S - p7
            float d  = __fmaf_rn(np6, lB, d1);   //   - p6*B
            float e  = __fmul_rn(lW, d);         // W*(...)
            float b  = __fmaf_rn(np3, t, c);     // c - p3*t
            float g  = __fmaf_rn(p8,  f, np9);   // p8*f - p9

            BW = fma2(pk2(g, e), BW, BW);        // {B+g*B, W+e*W}
            SG = fma2(pk2(b, a), SG, SG);        // {S+b*S, G+a*G}

            traj[2 * j]     = BW;
            traj[2 * j + 1] = SG;
        }
    }

    __syncthreads();

    // Parallel fan-out: shared (num_steps x float4) -> global (num_steps x 5).
    const float iv = y0[4];
    const float4* tr4 = (const float4*)traj;
    for (int r = threadIdx.x; r < num_steps; r += blockDim.x) {
        const float4 s = tr4[r];
        float* o = out + (size_t)r * 5;
        o[0] = s.x;
        o[1] = s.y;
        o[2] = s.z;
        o[3] = s.w;
        o[4] = iv;
    }
}

extern "C" void kernel_launch(void* const* d_in, const int* in_sizes, int n_in,
                              void* d_out, int out_size) {
    const float* y0     = (const float*)d_in[0];
    const float* params = (const float*)d_in[1];
    const int num_steps = out_size / 5;

    const size_t smem = (size_t)num_steps * 16;
    cudaFuncSetAttribute(bwsg_ode_kernel,
                         cudaFuncAttributeMaxDynamicSharedMemorySize,
                         (int)smem);
    bwsg_ode_kernel<<<1, 256, smem>>>(y0, params, (float*)d_out, num_steps);
}